// round 14
// baseline (speedup 1.0000x reference)
#include <cuda_runtime.h>
#include <cuda_fp16.h>
#include <math.h>

#define BB   8
#define NPTS 8192
#define SS   2048
#define CC   256
#define KNN  8

#define GRID 8
#define NCELL (GRID * GRID * GRID)
#define GLO  (-4.5f)
#define GH   (9.0f / GRID)          // 1.125

// Scratch (no allocation allowed)
__device__ __half g_featH[BB * SS * CC];        // [B][S][C] fp16, 8.4 MB
__device__ int    g_idx[BB * NPTS * KNN];       // 2 MB
__device__ float  g_w  [BB * NPTS * KNN];       // 2 MB
__device__ float4 g_binned[BB * SS];            // binned points (x,y,z,idx-bits)
__device__ int    g_cellstart[BB][NCELL + 1];   // sparse-point CSR offsets
__device__ int    g_qorder[BB * NPTS];          // queries sorted by home cell

// ---------------------------------------------------------------------------
// Kernel 0: transpose + fp16-convert sparse_feat [B,C,S] -> g_featH [B,S,C]
// ---------------------------------------------------------------------------
__global__ void transpose_feat_kernel(const float* __restrict__ feat) {
    __shared__ float tile[32][33];
    int b  = blockIdx.z;
    int s0 = blockIdx.x * 32;
    int c0 = blockIdx.y * 32;
    const float* src = feat + (size_t)b * CC * SS;

    #pragma unroll
    for (int i = threadIdx.y; i < 32; i += 8) {
        tile[i][threadIdx.x] = src[(size_t)(c0 + i) * SS + s0 + threadIdx.x];
    }
    __syncthreads();
    __half* dst = g_featH + (size_t)b * SS * CC;
    #pragma unroll
    for (int i = threadIdx.y; i < 32; i += 8) {
        dst[(size_t)(s0 + i) * CC + c0 + threadIdx.x] =
            __float2half(tile[threadIdx.x][i]);
    }
}

// ---------------------------------------------------------------------------
// Grid helpers (clamp into edge cells — safe for the pruning bound).
// ---------------------------------------------------------------------------
__device__ __forceinline__ int cell_of(float x, float y, float z) {
    int cx = (int)floorf((x - GLO) / GH);
    int cy = (int)floorf((y - GLO) / GH);
    int cz = (int)floorf((z - GLO) / GH);
    cx = min(max(cx, 0), GRID - 1);
    cy = min(max(cy, 0), GRID - 1);
    cz = min(max(cz, 0), GRID - 1);
    return (cx * GRID + cy) * GRID + cz;
}

// ---------------------------------------------------------------------------
// Kernel A: bin sparse points into the 8^3 grid (counting sort), 1 blk/batch.
// ---------------------------------------------------------------------------
__global__ void __launch_bounds__(512)
bin_kernel(const float* __restrict__ sxyz) {
    __shared__ int hist[NCELL];
    __shared__ int curs[NCELL];
    int b   = blockIdx.x;
    int tid = threadIdx.x;

    for (int c = tid; c < NCELL; c += 512) hist[c] = 0;
    __syncthreads();

    const float* sb = sxyz + (size_t)b * 3 * SS;
    float px[4], py[4], pz[4];
    int   pc[4];
    #pragma unroll
    for (int j = 0; j < 4; j++) {
        int s = tid * 4 + j;
        px[j] = sb[s];
        py[j] = sb[SS + s];
        pz[j] = sb[2 * SS + s];
        pc[j] = cell_of(px[j], py[j], pz[j]);
        atomicAdd(&hist[pc[j]], 1);
    }
    __syncthreads();

    if (tid == 0) {
        int run = 0;
        for (int c = 0; c < NCELL; c++) {
            int h = hist[c];
            curs[c] = run;
            g_cellstart[b][c] = run;
            run += h;
        }
        g_cellstart[b][NCELL] = run;
    }
    __syncthreads();

    #pragma unroll
    for (int j = 0; j < 4; j++) {
        int s = tid * 4 + j;
        int pos = atomicAdd(&curs[pc[j]], 1);
        g_binned[(size_t)b * SS + pos] =
            make_float4(px[j], py[j], pz[j], __int_as_float(s));
    }
}

// ---------------------------------------------------------------------------
// Kernel B: counting-sort QUERIES by home cell (warp-lane coherence).
// ---------------------------------------------------------------------------
__global__ void __launch_bounds__(1024)
qsort_kernel(const float* __restrict__ xyz) {
    __shared__ int hist[NCELL];
    __shared__ int curs[NCELL];
    int b   = blockIdx.x;
    int tid = threadIdx.x;

    for (int c = tid; c < NCELL; c += 1024) hist[c] = 0;
    __syncthreads();

    const float* xb = xyz + (size_t)b * 3 * NPTS;
    int qc[8];
    #pragma unroll
    for (int j = 0; j < 8; j++) {
        int n = tid * 8 + j;
        qc[j] = cell_of(xb[n], xb[NPTS + n], xb[2 * NPTS + n]);
        atomicAdd(&hist[qc[j]], 1);
    }
    __syncthreads();

    if (tid == 0) {
        int run = 0;
        for (int c = 0; c < NCELL; c++) {
            curs[c] = run;
            run += hist[c];
        }
    }
    __syncthreads();

    #pragma unroll
    for (int j = 0; j < 8; j++) {
        int n = tid * 8 + j;
        int pos = atomicAdd(&curs[qc[j]], 1);
        g_qorder[b * NPTS + pos] = n;
    }
}

// ---------------------------------------------------------------------------
// Kernel 1: grid KNN, TWO LANES PER QUERY — structure identical to the
// measured-best R12 kernel, EXCEPT candidates are read via __ldg from the
// L1/L2-resident 32KB g_binned table instead of a 32KB smem stage. This
// removes the 6-blocks/SM smem occupancy cap (25% -> ~60-80%) with an
// instruction profile byte-identical to R12.
// Direct (p-q)^2 metric (REQUIRED — R2 lesson). Margin/stop math proven
// in R9-R12; pair bound min(my_d8, partner_d8) is conservative-safe.
// ---------------------------------------------------------------------------
#define INSERT_NOVOTE(d, sidx)                                               \
    {                                                                        \
        bool c0 = (d) < dist[0];                                             \
        bool c1 = (d) < dist[1];                                             \
        bool c2 = (d) < dist[2];                                             \
        bool c3 = (d) < dist[3];                                             \
        bool c4 = (d) < dist[4];                                             \
        bool c5 = (d) < dist[5];                                             \
        bool c6 = (d) < dist[6];                                             \
        bool c7 = (d) < dist[7];                                             \
        float n0 = c1 ? dist[1] : (c0 ? (d) : dist[0]);                      \
        int   m0 = c1 ? nidx[1] : (c0 ? (sidx) : nidx[0]);                   \
        float n1 = c2 ? dist[2] : (c1 ? (d) : dist[1]);                      \
        int   m1 = c2 ? nidx[2] : (c1 ? (sidx) : nidx[1]);                   \
        float n2 = c3 ? dist[3] : (c2 ? (d) : dist[2]);                      \
        int   m2 = c3 ? nidx[3] : (c2 ? (sidx) : nidx[2]);                   \
        float n3 = c4 ? dist[4] : (c3 ? (d) : dist[3]);                      \
        int   m3 = c4 ? nidx[4] : (c3 ? (sidx) : nidx[3]);                   \
        float n4 = c5 ? dist[5] : (c4 ? (d) : dist[4]);                      \
        int   m4 = c5 ? nidx[5] : (c4 ? (sidx) : nidx[4]);                   \
        float n5 = c6 ? dist[6] : (c5 ? (d) : dist[5]);                      \
        int   m5 = c6 ? nidx[6] : (c5 ? (sidx) : nidx[5]);                   \
        float n6 = c7 ? dist[7] : (c6 ? (d) : dist[6]);                      \
        int   m6 = c7 ? nidx[7] : (c6 ? (sidx) : nidx[6]);                   \
        float n7 = c7 ? (d) : dist[7];                                       \
        int   m7 = c7 ? (sidx) : nidx[7];                                    \
        dist[0] = n0; nidx[0] = m0;                                          \
        dist[1] = n1; nidx[1] = m1;                                          \
        dist[2] = n2; nidx[2] = m2;                                          \
        dist[3] = n3; nidx[3] = m3;                                          \
        dist[4] = n4; nidx[4] = m4;                                          \
        dist[5] = n5; nidx[5] = m5;                                          \
        dist[6] = n6; nidx[6] = m6;                                          \
        dist[7] = n7; nidx[7] = m7;                                          \
    }

__global__ void __launch_bounds__(128)
knn_pair_kernel(const float* __restrict__ xyz) {
    __shared__ int cs[NCELL + 1];      // cell starts (2 KB)
    int b = blockIdx.y;
    for (int c = threadIdx.x; c <= NCELL; c += 128) cs[c] = g_cellstart[b][c];
    __syncthreads();

    const float4* gb = g_binned + (size_t)b * SS;
    int tid  = threadIdx.x;
    int sub  = tid & 1;                         // which half of candidates
    int qpos = blockIdx.x * 64 + (tid >> 1);    // 64 queries per block
    int n    = g_qorder[b * NPTS + qpos];

    const float* xb = xyz + (size_t)b * 3 * NPTS;
    float qx = xb[n];
    float qy = xb[NPTS + n];
    float qz = xb[2 * NPTS + n];

    int hx = min(max((int)floorf((qx - GLO) / GH), 0), GRID - 1);
    int hy = min(max((int)floorf((qy - GLO) / GH), 0), GRID - 1);
    int hz = min(max((int)floorf((qz - GLO) / GH), 0), GRID - 1);

    float dist[KNN];     // descending: dist[0] = partial 8th-best
    int   nidx[KNN];
    #pragma unroll
    for (int k = 0; k < KNN; k++) { dist[k] = 3.4e38f; nidx[k] = 0; }

    bool done = false;
    for (int r = 0; r < GRID; r++) {
        if (!done) {
            int lx = max(hx - r, 0), ux = min(hx + r, GRID - 1);
            int ly = max(hy - r, 0), uy = min(hy + r, GRID - 1);
            int lz = max(hz - r, 0), uz = min(hz + r, GRID - 1);

            for (int zx = lx; zx <= ux; zx++) {
                int ax = ::abs(zx - hx);
                for (int zy = ly; zy <= uy; zy++) {
                    int axy = max(ax, ::abs(zy - hy));
                    for (int zz = lz; zz <= uz; zz++) {
                        int cheb = max(axy, ::abs(zz - hz));
                        if (cheb != r) continue;     // only the new shell
                        int cell = (zx * GRID + zy) * GRID + zz;
                        int j0 = cs[cell], j1 = cs[cell + 1];
                        for (int j = j0 + sub; j < j1; j += 2) {
                            float4 p = __ldg(&gb[j]);
                            float dx = qx - p.x;
                            float dy = qy - p.y;
                            float dz = qz - p.z;
                            float d = fmaf(dx, dx, fmaf(dy, dy, dz * dz));
                            if (d < dist[0]) {
                                int sidx = __float_as_int(p.w);
                                INSERT_NOVOTE(d, sidx)
                            }
                        }
                    }
                }
            }

            // Exact margin (identical to R10/R12); stop bound over the pair.
            float m = 3.4e38f;
            if (lx > 0)        m = fminf(m, qx - (lx * GH + GLO));
            if (ux < GRID - 1) m = fminf(m, ((ux + 1) * GH + GLO) - qx);
            if (ly > 0)        m = fminf(m, qy - (ly * GH + GLO));
            if (uy < GRID - 1) m = fminf(m, ((uy + 1) * GH + GLO) - qy);
            if (lz > 0)        m = fminf(m, qz - (lz * GH + GLO));
            if (uz < GRID - 1) m = fminf(m, ((uz + 1) * GH + GLO) - qz);
            float pd8 = __shfl_xor_sync(0xffffffffu, dist[0], 1);
            float bound8 = fminf(dist[0], pd8);
            done = (m >= 3.4e38f) || (m > 0.0f && bound8 <= m * m);
        } else {
            // keep shuffle in uniform control flow for the pair
            (void)__shfl_xor_sync(0xffffffffu, dist[0], 1);
        }
        if (__all_sync(0xffffffffu, done)) break;
    }

    // Exchange partner's partial top-8 and half-clean merge (R8-proven):
    // ascending mine a[i] = dist[7-i]; partner's b[7-i] = partner dist[i].
    float pdl[KNN];
    int   pil[KNN];
    #pragma unroll
    for (int k = 0; k < KNN; k++) {
        pdl[k] = __shfl_xor_sync(0xffffffffu, dist[k], 1);
        pil[k] = __shfl_xor_sync(0xffffffffu, nidx[k], 1);
    }

    if (sub == 0) {
        float md[KNN];
        int   mi[KNN];
        #pragma unroll
        for (int i = 0; i < KNN; i++) {
            float a = dist[KNN - 1 - i];
            int   aidx = nidx[KNN - 1 - i];
            bool ta = a <= pdl[i];
            md[i] = ta ? a : pdl[i];
            mi[i] = ta ? aidx : pil[i];
        }

        // inverse-distance weights (permutation-invariant)
        float inv[KNN];
        float ws = 0.0f;
        #pragma unroll
        for (int k = 0; k < KNN; k++) {
            float dd = sqrtf(md[k]);
            dd = fmaxf(dd, 1e-10f);
            inv[k] = 1.0f / dd;
            ws += inv[k];
        }
        float rws = 1.0f / ws;

        int base = (b * NPTS + n) * KNN;
        #pragma unroll
        for (int k = 0; k < KNN; k++) {
            g_idx[base + k] = mi[k];
            g_w[base + k]   = inv[k] * rws;
        }
    }
}

// ---------------------------------------------------------------------------
// Kernel 2: weighted feature interpolation, fp16 gathers, fp32 accumulate.
// ---------------------------------------------------------------------------
__global__ void interp_kernel(float* __restrict__ out) {
    __shared__ float tile[32][CC + 1];   // 32 x 257 floats
    __shared__ int   s_idx[32][KNN];
    __shared__ float s_w[32][KNN];

    int b  = blockIdx.y;
    int n0 = blockIdx.x * 32;
    int tid = threadIdx.x;

    if (tid < 32 * KNN) {
        int nn = tid / KNN;
        int kk = tid % KNN;
        int base = (b * NPTS + n0 + nn) * KNN;
        s_idx[nn][kk] = g_idx[base + kk];
        s_w[nn][kk]   = g_w[base + kk];
    }
    __syncthreads();

    int tc    = tid & 63;
    int qbase = tid >> 6;
    const __half* fb = g_featH + (size_t)b * SS * CC + tc * 4;

    #pragma unroll
    for (int q = qbase; q < 32; q += 16) {
        float a0 = 0.f, a1 = 0.f, a2 = 0.f, a3 = 0.f;
        #pragma unroll
        for (int k = 0; k < KNN; k++) {
            int   si = s_idx[q][k];
            float wt = s_w[q][k];
            uint2 raw = *(const uint2*)(fb + (size_t)si * CC);
            __half2 h0 = *reinterpret_cast<__half2*>(&raw.x);
            __half2 h1 = *reinterpret_cast<__half2*>(&raw.y);
            float2 f0 = __half22float2(h0);
            float2 f1 = __half22float2(h1);
            a0 = fmaf(wt, f0.x, a0);
            a1 = fmaf(wt, f0.y, a1);
            a2 = fmaf(wt, f1.x, a2);
            a3 = fmaf(wt, f1.y, a3);
        }
        int c = tc * 4;
        tile[q][c + 0] = a0;
        tile[q][c + 1] = a1;
        tile[q][c + 2] = a2;
        tile[q][c + 3] = a3;
    }
    __syncthreads();

    int lane = tid & 31;
    int w    = tid >> 5;
    float* ob = out + (size_t)b * CC * NPTS + n0 + lane;
    #pragma unroll
    for (int j = 0; j < 8; j++) {
        int c = w + j * 32;
        ob[(size_t)c * NPTS] = tile[lane][c];
    }
}

// ---------------------------------------------------------------------------
extern "C" void kernel_launch(void* const* d_in, const int* in_sizes, int n_in,
                              void* d_out, int out_size) {
    const float* xyz         = (const float*)d_in[0];  // [B,3,N]
    const float* sparse_xyz  = (const float*)d_in[1];  // [B,3,S]
    const float* sparse_feat = (const float*)d_in[2];  // [B,C,S]
    float* out = (float*)d_out;                        // [B,C,N]

    transpose_feat_kernel<<<dim3(SS / 32, CC / 32, BB), dim3(32, 8)>>>(sparse_feat);
    bin_kernel<<<BB, 512>>>(sparse_xyz);
    qsort_kernel<<<BB, 1024>>>(xyz);
    knn_pair_kernel<<<dim3(NPTS / 64, BB), 128>>>(xyz);
    interp_kernel<<<dim3(NPTS / 32, BB), 1024>>>(out);
}

// round 15
// speedup vs baseline: 1.1978x; 1.1978x over previous
#include <cuda_runtime.h>
#include <cuda_fp16.h>
#include <math.h>

#define BB   8
#define NPTS 8192
#define SS   2048
#define CC   256
#define KNN  8

#define GRID 8
#define NCELL (GRID * GRID * GRID)
#define GLO  (-4.5f)
#define GH   (9.0f / GRID)          // 1.125

// Scratch (no allocation allowed)
__device__ __half g_featH[BB * SS * CC];        // [B][S][C] fp16, 8.4 MB
__device__ int    g_idx[BB * NPTS * KNN];       // 2 MB
__device__ float  g_w  [BB * NPTS * KNN];       // 2 MB
__device__ float4 g_binned[BB * SS];            // binned points (x,y,z,idx-bits)
__device__ int    g_cellstart[BB][NCELL + 1];   // sparse-point CSR offsets
__device__ int    g_qorder[BB * NPTS];          // queries sorted by home cell

// ---------------------------------------------------------------------------
// Kernel 0: transpose + fp16-convert sparse_feat [B,C,S] -> g_featH [B,S,C]
// ---------------------------------------------------------------------------
__global__ void transpose_feat_kernel(const float* __restrict__ feat) {
    __shared__ float tile[32][33];
    int b  = blockIdx.z;
    int s0 = blockIdx.x * 32;
    int c0 = blockIdx.y * 32;
    const float* src = feat + (size_t)b * CC * SS;

    #pragma unroll
    for (int i = threadIdx.y; i < 32; i += 8) {
        tile[i][threadIdx.x] = src[(size_t)(c0 + i) * SS + s0 + threadIdx.x];
    }
    __syncthreads();
    __half* dst = g_featH + (size_t)b * SS * CC;
    #pragma unroll
    for (int i = threadIdx.y; i < 32; i += 8) {
        dst[(size_t)(s0 + i) * CC + c0 + threadIdx.x] =
            __float2half(tile[threadIdx.x][i]);
    }
}

// ---------------------------------------------------------------------------
// Grid helpers (clamp into edge cells — safe for the pruning bound).
// ---------------------------------------------------------------------------
__device__ __forceinline__ int cell_of(float x, float y, float z) {
    int cx = (int)floorf((x - GLO) / GH);
    int cy = (int)floorf((y - GLO) / GH);
    int cz = (int)floorf((z - GLO) / GH);
    cx = min(max(cx, 0), GRID - 1);
    cy = min(max(cy, 0), GRID - 1);
    cz = min(max(cz, 0), GRID - 1);
    return (cx * GRID + cy) * GRID + cz;
}

// ---------------------------------------------------------------------------
// Kernel A: bin sparse points into the 8^3 grid (counting sort), 1 blk/batch.
// ---------------------------------------------------------------------------
__global__ void __launch_bounds__(512)
bin_kernel(const float* __restrict__ sxyz) {
    __shared__ int hist[NCELL];
    __shared__ int curs[NCELL];
    int b   = blockIdx.x;
    int tid = threadIdx.x;

    for (int c = tid; c < NCELL; c += 512) hist[c] = 0;
    __syncthreads();

    const float* sb = sxyz + (size_t)b * 3 * SS;
    float px[4], py[4], pz[4];
    int   pc[4];
    #pragma unroll
    for (int j = 0; j < 4; j++) {
        int s = tid * 4 + j;
        px[j] = sb[s];
        py[j] = sb[SS + s];
        pz[j] = sb[2 * SS + s];
        pc[j] = cell_of(px[j], py[j], pz[j]);
        atomicAdd(&hist[pc[j]], 1);
    }
    __syncthreads();

    if (tid == 0) {
        int run = 0;
        for (int c = 0; c < NCELL; c++) {
            int h = hist[c];
            curs[c] = run;
            g_cellstart[b][c] = run;
            run += h;
        }
        g_cellstart[b][NCELL] = run;
    }
    __syncthreads();

    #pragma unroll
    for (int j = 0; j < 4; j++) {
        int s = tid * 4 + j;
        int pos = atomicAdd(&curs[pc[j]], 1);
        g_binned[(size_t)b * SS + pos] =
            make_float4(px[j], py[j], pz[j], __int_as_float(s));
    }
}

// ---------------------------------------------------------------------------
// Kernel B: counting-sort QUERIES by home cell (warp-lane coherence).
// ---------------------------------------------------------------------------
__global__ void __launch_bounds__(1024)
qsort_kernel(const float* __restrict__ xyz) {
    __shared__ int hist[NCELL];
    __shared__ int curs[NCELL];
    int b   = blockIdx.x;
    int tid = threadIdx.x;

    for (int c = tid; c < NCELL; c += 1024) hist[c] = 0;
    __syncthreads();

    const float* xb = xyz + (size_t)b * 3 * NPTS;
    int qc[8];
    #pragma unroll
    for (int j = 0; j < 8; j++) {
        int n = tid * 8 + j;
        qc[j] = cell_of(xb[n], xb[NPTS + n], xb[2 * NPTS + n]);
        atomicAdd(&hist[qc[j]], 1);
    }
    __syncthreads();

    if (tid == 0) {
        int run = 0;
        for (int c = 0; c < NCELL; c++) {
            curs[c] = run;
            run += hist[c];
        }
    }
    __syncthreads();

    #pragma unroll
    for (int j = 0; j < 8; j++) {
        int n = tid * 8 + j;
        int pos = atomicAdd(&curs[qc[j]], 1);
        g_qorder[b * NPTS + pos] = n;
    }
}

// ---------------------------------------------------------------------------
// Kernel 1: grid KNN, TWO LANES PER QUERY, smem-staged candidates (R12
// structure — measured best), but 256-THREAD BLOCKS: same 34KB smem per
// block now carries 8 warps instead of 4, doubling warps/SM under the
// 6-block smem cap (occ 25% -> ~45%). Instruction stream per query is
// byte-identical to R12. Direct (p-q)^2 metric (REQUIRED — R2 lesson);
// margin/stop math proven R9-R12.
// ---------------------------------------------------------------------------
#define INSERT_NOVOTE(d, sidx)                                               \
    {                                                                        \
        bool c0 = (d) < dist[0];                                             \
        bool c1 = (d) < dist[1];                                             \
        bool c2 = (d) < dist[2];                                             \
        bool c3 = (d) < dist[3];                                             \
        bool c4 = (d) < dist[4];                                             \
        bool c5 = (d) < dist[5];                                             \
        bool c6 = (d) < dist[6];                                             \
        bool c7 = (d) < dist[7];                                             \
        float n0 = c1 ? dist[1] : (c0 ? (d) : dist[0]);                      \
        int   m0 = c1 ? nidx[1] : (c0 ? (sidx) : nidx[0]);                   \
        float n1 = c2 ? dist[2] : (c1 ? (d) : dist[1]);                      \
        int   m1 = c2 ? nidx[2] : (c1 ? (sidx) : nidx[1]);                   \
        float n2 = c3 ? dist[3] : (c2 ? (d) : dist[2]);                      \
        int   m2 = c3 ? nidx[3] : (c2 ? (sidx) : nidx[2]);                   \
        float n3 = c4 ? dist[4] : (c3 ? (d) : dist[3]);                      \
        int   m3 = c4 ? nidx[4] : (c3 ? (sidx) : nidx[3]);                   \
        float n4 = c5 ? dist[5] : (c4 ? (d) : dist[4]);                      \
        int   m4 = c5 ? nidx[5] : (c4 ? (sidx) : nidx[4]);                   \
        float n5 = c6 ? dist[6] : (c5 ? (d) : dist[5]);                      \
        int   m5 = c6 ? nidx[6] : (c5 ? (sidx) : nidx[5]);                   \
        float n6 = c7 ? dist[7] : (c6 ? (d) : dist[6]);                      \
        int   m6 = c7 ? nidx[7] : (c6 ? (sidx) : nidx[6]);                   \
        float n7 = c7 ? (d) : dist[7];                                       \
        int   m7 = c7 ? (sidx) : nidx[7];                                    \
        dist[0] = n0; nidx[0] = m0;                                          \
        dist[1] = n1; nidx[1] = m1;                                          \
        dist[2] = n2; nidx[2] = m2;                                          \
        dist[3] = n3; nidx[3] = m3;                                          \
        dist[4] = n4; nidx[4] = m4;                                          \
        dist[5] = n5; nidx[5] = m5;                                          \
        dist[6] = n6; nidx[6] = m6;                                          \
        dist[7] = n7; nidx[7] = m7;                                          \
    }

__global__ void __launch_bounds__(256)
knn_pair_kernel(const float* __restrict__ xyz) {
    __shared__ float4 sp[SS];          // binned points, 32 KB
    __shared__ int    cs[NCELL + 1];   // cell starts, 2 KB
    int b = blockIdx.y;

    {
        const float4* gb = g_binned + (size_t)b * SS;
        for (int s = threadIdx.x; s < SS; s += 256) sp[s] = gb[s];
        for (int c = threadIdx.x; c <= NCELL; c += 256) cs[c] = g_cellstart[b][c];
    }
    __syncthreads();

    int tid  = threadIdx.x;
    int sub  = tid & 1;                          // which half of candidates
    int qpos = blockIdx.x * 128 + (tid >> 1);    // 128 queries per block
    int n    = g_qorder[b * NPTS + qpos];

    const float* xb = xyz + (size_t)b * 3 * NPTS;
    float qx = xb[n];
    float qy = xb[NPTS + n];
    float qz = xb[2 * NPTS + n];

    int hx = min(max((int)floorf((qx - GLO) / GH), 0), GRID - 1);
    int hy = min(max((int)floorf((qy - GLO) / GH), 0), GRID - 1);
    int hz = min(max((int)floorf((qz - GLO) / GH), 0), GRID - 1);

    float dist[KNN];     // descending: dist[0] = partial 8th-best
    int   nidx[KNN];
    #pragma unroll
    for (int k = 0; k < KNN; k++) { dist[k] = 3.4e38f; nidx[k] = 0; }

    bool done = false;
    for (int r = 0; r < GRID; r++) {
        if (!done) {
            int lx = max(hx - r, 0), ux = min(hx + r, GRID - 1);
            int ly = max(hy - r, 0), uy = min(hy + r, GRID - 1);
            int lz = max(hz - r, 0), uz = min(hz + r, GRID - 1);

            for (int zx = lx; zx <= ux; zx++) {
                int ax = ::abs(zx - hx);
                for (int zy = ly; zy <= uy; zy++) {
                    int axy = max(ax, ::abs(zy - hy));
                    for (int zz = lz; zz <= uz; zz++) {
                        int cheb = max(axy, ::abs(zz - hz));
                        if (cheb != r) continue;     // only the new shell
                        int cell = (zx * GRID + zy) * GRID + zz;
                        int j0 = cs[cell], j1 = cs[cell + 1];
                        for (int j = j0 + sub; j < j1; j += 2) {
                            float4 p = sp[j];
                            float dx = qx - p.x;
                            float dy = qy - p.y;
                            float dz = qz - p.z;
                            float d = fmaf(dx, dx, fmaf(dy, dy, dz * dz));
                            if (d < dist[0]) {
                                int sidx = __float_as_int(p.w);
                                INSERT_NOVOTE(d, sidx)
                            }
                        }
                    }
                }
            }

            // Exact margin (identical to R10/R12); stop bound over the pair.
            float m = 3.4e38f;
            if (lx > 0)        m = fminf(m, qx - (lx * GH + GLO));
            if (ux < GRID - 1) m = fminf(m, ((ux + 1) * GH + GLO) - qx);
            if (ly > 0)        m = fminf(m, qy - (ly * GH + GLO));
            if (uy < GRID - 1) m = fminf(m, ((uy + 1) * GH + GLO) - qy);
            if (lz > 0)        m = fminf(m, qz - (lz * GH + GLO));
            if (uz < GRID - 1) m = fminf(m, ((uz + 1) * GH + GLO) - qz);
            float pd8 = __shfl_xor_sync(0xffffffffu, dist[0], 1);
            float bound8 = fminf(dist[0], pd8);
            done = (m >= 3.4e38f) || (m > 0.0f && bound8 <= m * m);
        } else {
            // keep shuffle in uniform control flow for the pair
            (void)__shfl_xor_sync(0xffffffffu, dist[0], 1);
        }
        if (__all_sync(0xffffffffu, done)) break;
    }

    // Exchange partner's partial top-8 and half-clean merge (R8-proven):
    // ascending mine a[i] = dist[7-i]; partner's b[7-i] = partner dist[i].
    float pdl[KNN];
    int   pil[KNN];
    #pragma unroll
    for (int k = 0; k < KNN; k++) {
        pdl[k] = __shfl_xor_sync(0xffffffffu, dist[k], 1);
        pil[k] = __shfl_xor_sync(0xffffffffu, nidx[k], 1);
    }

    if (sub == 0) {
        float md[KNN];
        int   mi[KNN];
        #pragma unroll
        for (int i = 0; i < KNN; i++) {
            float a = dist[KNN - 1 - i];
            int   aidx = nidx[KNN - 1 - i];
            bool ta = a <= pdl[i];
            md[i] = ta ? a : pdl[i];
            mi[i] = ta ? aidx : pil[i];
        }

        // inverse-distance weights (permutation-invariant)
        float inv[KNN];
        float ws = 0.0f;
        #pragma unroll
        for (int k = 0; k < KNN; k++) {
            float dd = sqrtf(md[k]);
            dd = fmaxf(dd, 1e-10f);
            inv[k] = 1.0f / dd;
            ws += inv[k];
        }
        float rws = 1.0f / ws;

        int base = (b * NPTS + n) * KNN;
        #pragma unroll
        for (int k = 0; k < KNN; k++) {
            g_idx[base + k] = mi[k];
            g_w[base + k]   = inv[k] * rws;
        }
    }
}

// ---------------------------------------------------------------------------
// Kernel 2: weighted feature interpolation, fp16 gathers, fp32 accumulate.
// ---------------------------------------------------------------------------
__global__ void interp_kernel(float* __restrict__ out) {
    __shared__ float tile[32][CC + 1];   // 32 x 257 floats
    __shared__ int   s_idx[32][KNN];
    __shared__ float s_w[32][KNN];

    int b  = blockIdx.y;
    int n0 = blockIdx.x * 32;
    int tid = threadIdx.x;

    if (tid < 32 * KNN) {
        int nn = tid / KNN;
        int kk = tid % KNN;
        int base = (b * NPTS + n0 + nn) * KNN;
        s_idx[nn][kk] = g_idx[base + kk];
        s_w[nn][kk]   = g_w[base + kk];
    }
    __syncthreads();

    int tc    = tid & 63;
    int qbase = tid >> 6;
    const __half* fb = g_featH + (size_t)b * SS * CC + tc * 4;

    #pragma unroll
    for (int q = qbase; q < 32; q += 16) {
        float a0 = 0.f, a1 = 0.f, a2 = 0.f, a3 = 0.f;
        #pragma unroll
        for (int k = 0; k < KNN; k++) {
            int   si = s_idx[q][k];
            float wt = s_w[q][k];
            uint2 raw = *(const uint2*)(fb + (size_t)si * CC);
            __half2 h0 = *reinterpret_cast<__half2*>(&raw.x);
            __half2 h1 = *reinterpret_cast<__half2*>(&raw.y);
            float2 f0 = __half22float2(h0);
            float2 f1 = __half22float2(h1);
            a0 = fmaf(wt, f0.x, a0);
            a1 = fmaf(wt, f0.y, a1);
            a2 = fmaf(wt, f1.x, a2);
            a3 = fmaf(wt, f1.y, a3);
        }
        int c = tc * 4;
        tile[q][c + 0] = a0;
        tile[q][c + 1] = a1;
        tile[q][c + 2] = a2;
        tile[q][c + 3] = a3;
    }
    __syncthreads();

    int lane = tid & 31;
    int w    = tid >> 5;
    float* ob = out + (size_t)b * CC * NPTS + n0 + lane;
    #pragma unroll
    for (int j = 0; j < 8; j++) {
        int c = w + j * 32;
        ob[(size_t)c * NPTS] = tile[lane][c];
    }
}

// ---------------------------------------------------------------------------
extern "C" void kernel_launch(void* const* d_in, const int* in_sizes, int n_in,
                              void* d_out, int out_size) {
    const float* xyz         = (const float*)d_in[0];  // [B,3,N]
    const float* sparse_xyz  = (const float*)d_in[1];  // [B,3,S]
    const float* sparse_feat = (const float*)d_in[2];  // [B,C,S]
    float* out = (float*)d_out;                        // [B,C,N]

    transpose_feat_kernel<<<dim3(SS / 32, CC / 32, BB), dim3(32, 8)>>>(sparse_feat);
    bin_kernel<<<BB, 512>>>(sparse_xyz);
    qsort_kernel<<<BB, 1024>>>(xyz);
    knn_pair_kernel<<<dim3(NPTS / 128, BB), 256>>>(xyz);
    interp_kernel<<<dim3(NPTS / 32, BB), 1024>>>(out);
}